// round 13
// baseline (speedup 1.0000x reference)
#include <cuda_runtime.h>
#include <cuda_bf16.h>

// Upscale_15358803050749: upfirdn2d up=2, 4x4 kernel [1,3,3,1]^2, gain 4.
// x: (8,128,128,128) f32 -> out: (8,128,256,256) f32.
//
// Polyphase (reference's dilated conv, pad0=2), separably factored:
//   K[v][u] = C[v]*D[u],  D[u]=K[0][u],  C[v]=K[v][0]/K[0][0]  (C0==1)
//   horiz: out col 2i   = D3*x[i-1] + D1*x[i]
//          out col 2i+1 = D2*x[i]   + D0*x[i+1]
//   vert : out row 2r   = C3*row(r-1) + C1*row(r)
//          out row 2r+1 = C2*row(r)   + row(r+1)
//
// R13 = R12 (contiguous stores = the R12 breakthrough) + sm_103a 256-bit
// stores. One warp = one unit (2 input rows -> 4 output rows, full width):
//   - thread owns 4 input cols (1 LDG.128 per row, 4 rows)
//   - vertical combine in regs -> T[4 rows][4 vals]
//   - minimal halo exchange: only first/last combined value per row via
//     smem (2 STS.32 + 2 LDS.32, conflict-free, lane+-1), __syncwarp only
//   - one st.global.cs.v8.f32 per output row: warp writes a full
//     contiguous 1KB row, full sectors, 1 instruction

#define W_IN   128
#define H_IN   128
#define W_OUT  256
#define NC     1024          // 8 * 128 planes
#define RYP    64            // units per plane (2 input rows each)

__device__ __forceinline__ void stg256_cs(float* p,
                                          float o0, float o1, float o2, float o3,
                                          float o4, float o5, float o6, float o7) {
    asm volatile(
        "st.global.cs.v8.f32 [%0], {%1,%2,%3,%4,%5,%6,%7,%8};"
        :: "l"(p), "f"(o0), "f"(o1), "f"(o2), "f"(o3),
           "f"(o4), "f"(o5), "f"(o6), "f"(o7)
        : "memory");
}

__global__ __launch_bounds__(128, 8)
void Upscale_15358803050749_kernel(const float* __restrict__ x,
                                   const float* __restrict__ k,
                                   float* __restrict__ out) {
    __shared__ float smL[4][4][32];   // [warp][out-row][lane] = thread's T[3]
    __shared__ float smR[4][4][32];   // [warp][out-row][lane] = thread's T[0]

    int tid  = threadIdx.x;
    int lane = tid & 31;
    int wid  = tid >> 5;
    int unit = (blockIdx.x * blockDim.x + tid) >> 5;   // global warp = unit
    int ry   = unit & (RYP - 1);
    int pl   = unit >> 6;                 // plane 0..NC-1
    int iy0  = ry * 2;
    int cx   = lane * 4;                  // input col base

    const float* xp = x   + pl * (H_IN * W_IN);
    float*       op = out + pl * (256 * W_OUT);

    // ---- 4 independent LDG.128 (rows iy0-1 .. iy0+2) ----
    bool vm = (iy0 > 0);
    bool vc = (iy0 + 2 < H_IN);
    const float* pm = xp + (vm ? (iy0 - 1) : 0) * W_IN + cx;
    const float* pa = xp + iy0 * W_IN + cx;
    const float* pb = pa + W_IN;
    const float* pc = xp + (vc ? (iy0 + 2) : 0) * W_IN + cx;

    float4 Vm = *reinterpret_cast<const float4*>(pm);
    float4 Va = *reinterpret_cast<const float4*>(pa);
    float4 Vb = *reinterpret_cast<const float4*>(pb);
    float4 Vc = *reinterpret_cast<const float4*>(pc);

    // ---- separable factors (overlaps load latency) ----
    float D0 = __ldg(k + 0), D1 = __ldg(k + 1), D2 = __ldg(k + 2), D3 = __ldg(k + 3);
    float inv = 1.0f / D0;
    float C1 = __ldg(k + 4)  * inv;
    float C2 = __ldg(k + 8)  * inv;
    float C3 = __ldg(k + 12) * inv;     // C0 == 1

    float zm = vm ? 1.f : 0.f;
    float zc = vc ? 1.f : 0.f;
    Vm.x *= zm; Vm.y *= zm; Vm.z *= zm; Vm.w *= zm;
    Vc.x *= zc; Vc.y *= zc; Vc.z *= zc; Vc.w *= zc;

    // ---- vertical combine on own 4 columns -> T[4 out rows][4 vals] ----
    float T[4][4];
    {
        const float mA[4] = { Vm.x, Vm.y, Vm.z, Vm.w };
        const float aA[4] = { Va.x, Va.y, Va.z, Va.w };
        const float bA[4] = { Vb.x, Vb.y, Vb.z, Vb.w };
        const float cA[4] = { Vc.x, Vc.y, Vc.z, Vc.w };
        #pragma unroll
        for (int j = 0; j < 4; j++) {
            T[0][j] = C3 * mA[j] + C1 * aA[j];   // out row 2*iy0
            T[1][j] = C2 * aA[j] + bA[j];        // out row 2*iy0+1
            T[2][j] = C3 * aA[j] + C1 * bA[j];   // out row 2*iy0+2
            T[3][j] = C2 * bA[j] + cA[j];        // out row 2*iy0+3
        }
    }

    // ---- minimal halo exchange: first/last combined value per row ----
    #pragma unroll
    for (int s = 0; s < 4; s++) {
        smL[wid][s][lane] = T[s][3];
        smR[wid][s][lane] = T[s][0];
    }
    __syncwarp();

    bool gl = (lane > 0);
    bool gr = (lane < 31);
    float* q = op + (2 * iy0) * W_OUT + 8 * lane;   // 32B-aligned, contiguous

    // ---- horizontal transform + one 256-bit store per output row ----
    #pragma unroll
    for (int s = 0; s < 4; s++) {
        float hl = gl ? smL[wid][s][lane - 1] : 0.f;  // T[cx-1] (combined)
        float hr = gr ? smR[wid][s][lane + 1] : 0.f;  // T[cx+4] (combined)
        float t0 = T[s][0], t1 = T[s][1], t2 = T[s][2], t3 = T[s][3];
        float o0 = D3 * hl + D1 * t0;    // out col 8l   (even, i=4l)
        float o1 = D2 * t0 + D0 * t1;    // out col 8l+1
        float o2 = D3 * t0 + D1 * t1;    // out col 8l+2 (even, i=4l+1)
        float o3 = D2 * t1 + D0 * t2;    // out col 8l+3
        float o4 = D3 * t1 + D1 * t2;    // out col 8l+4 (even, i=4l+2)
        float o5 = D2 * t2 + D0 * t3;    // out col 8l+5
        float o6 = D3 * t2 + D1 * t3;    // out col 8l+6 (even, i=4l+3)
        float o7 = D2 * t3 + D0 * hr;    // out col 8l+7
        stg256_cs(q + s * W_OUT, o0, o1, o2, o3, o4, o5, o6, o7);
    }
}

extern "C" void kernel_launch(void* const* d_in, const int* in_sizes, int n_in,
                              void* d_out, int out_size) {
    const float* x = (const float*)d_in[0];   // (8,128,128,128)
    const float* k = (const float*)d_in[1];   // (4,4)
    float* out = (float*)d_out;               // (8,128,256,256)

    // units = NC * RYP = 65536 warps ; threads = 2,097,152 ; blocks = 16384
    int threads = 128;
    int blocks = (NC * RYP * 32) / threads;
    Upscale_15358803050749_kernel<<<blocks, threads>>>(x, k, out);
}